// round 9
// baseline (speedup 1.0000x reference)
#include <cuda_runtime.h>
#include <math.h>

#define DIM_EI  4096
#define DIM_CA3 8192
#define DIM_CA1 8192
#define DIM_EO  4096

static constexpr float BETA  = 10.0f;
static constexpr float ALPHA = 0.01f;

// ---------------- device scratch ----------------
__device__ float g_h1[DIM_CA3];
__device__ float g_h3[DIM_CA1];
__device__ float g_h2[DIM_CA1];
__device__ float g_h4[DIM_EO];
__device__ float g_xca3[DIM_CA3];
__device__ float g_IS[DIM_CA1];
__device__ float g_xca1[DIM_CA1];
__device__ int   g_nnz_idx[DIM_CA3];
__device__ float g_nnz_val[DIM_CA3];
__device__ int   g_nnz_cnt;
__device__ unsigned g_ctr_out;   // zero-init; self-resets each replay

// ---------------- helpers ----------------
__device__ __forceinline__ unsigned f2u(float f) {
    unsigned u = __float_as_uint(f);
    return (u & 0x80000000u) ? ~u : (u | 0x80000000u);
}
__device__ __forceinline__ float u2f(unsigned u) {
    return __uint_as_float((u & 0x80000000u) ? (u & 0x7fffffffu) : ~u);
}
__device__ __forceinline__ float sigm(float z) { return 1.0f / (1.0f + expf(-z)); }

// Conflict-free smem histogram add: aggregate equal bins within the warp.
__device__ __forceinline__ void hist_add(unsigned* s_hist, int bin, bool pred) {
    unsigned active = __ballot_sync(0xffffffffu, pred);
    if (pred) {
        unsigned mask = __match_any_sync(active, bin);
        int leader = __ffs(mask) - 1;
        if ((int)(threadIdx.x & 31) == leader)
            atomicAdd(&s_hist[bin], (unsigned)__popc(mask));
    }
}

// Warp 0 finds the bin containing the k-th largest from a 256-bin histogram.
// 8 bins/lane in registers + shfl suffix scan; writes s_bin / s_k.
__device__ __forceinline__ void find_bin_warp0(const unsigned* s_hist, int k,
                                               int* s_bin, int* s_k) {
    if (threadIdx.x < 32) {
        int lane = threadIdx.x;
        unsigned b[8]; unsigned tot = 0;
        #pragma unroll
        for (int j = 0; j < 8; j++) { b[j] = s_hist[lane * 8 + j]; tot += b[j]; }
        unsigned suf = tot;                       // inclusive suffix over lanes
        #pragma unroll
        for (int o = 1; o < 32; o <<= 1) {
            unsigned n = __shfl_down_sync(0xffffffffu, suf, o);
            if (lane + o < 32) suf += n;
        }
        unsigned above = suf - tot;               // count in bins of higher lanes
        unsigned ge[8]; unsigned run = above;
        #pragma unroll
        for (int j = 7; j >= 0; j--) { run += b[j]; ge[j] = run; }
        unsigned gt = above;                      // count strictly above bin j
        #pragma unroll
        for (int j = 7; j >= 0; j--) {
            if (ge[j] >= (unsigned)k && gt < (unsigned)k) {
                *s_bin = lane * 8 + j;
                *s_k   = k - (int)gt;
            }
            gt = ge[j];
        }
    }
}

// Exact K-th largest, register values, 3 barriers/pass. blockDim >= 256.
template<int M>
__device__ float kth_fast_reg(const unsigned* uv, int K) {
    __shared__ unsigned s_hist[256];
    __shared__ int s_bin, s_k;
    unsigned prefix = 0;
    int k = K;
    #pragma unroll
    for (int shift = 24; shift >= 0; shift -= 8) {
        if (threadIdx.x < 256) s_hist[threadIdx.x] = 0;
        __syncthreads();
        unsigned hi = (shift == 24) ? 0u : (0xFFFFFFFFu << (shift + 8));
        #pragma unroll
        for (int j = 0; j < M; j++) {
            unsigned u = uv[j];
            hist_add(s_hist, (u >> shift) & 255, (u & hi) == prefix);
        }
        __syncthreads();
        find_bin_warp0(s_hist, k, &s_bin, &s_k);
        __syncthreads();
        prefix |= ((unsigned)s_bin) << shift;
        k = s_k;
    }
    return u2f(prefix);
}

// Exact K-th largest of x[0..n), global-read variant (blockDim >= 256).
__device__ float kth_fast_global(const float* __restrict__ x, int n, int K) {
    __shared__ unsigned s_hist[256];
    __shared__ int s_bin, s_k;
    unsigned prefix = 0;
    int k = K;
    #pragma unroll
    for (int shift = 24; shift >= 0; shift -= 8) {
        if (threadIdx.x < 256) s_hist[threadIdx.x] = 0;
        __syncthreads();
        unsigned hi = (shift == 24) ? 0u : (0xFFFFFFFFu << (shift + 8));
        for (int i = threadIdx.x; i < n; i += blockDim.x) {
            unsigned u = f2u(x[i]);
            hist_add(s_hist, (u >> shift) & 255, (u & hi) == prefix);
        }
        __syncthreads();
        find_bin_warp0(s_hist, k, &s_bin, &s_k);
        __syncthreads();
        prefix |= ((unsigned)s_bin) << shift;
        k = s_k;
    }
    return u2f(prefix);
}

// ---------------- K1: h1 = W_ei_ca3 @ x, h3 = W_ei_ca1 @ x (one warp/row) -------------
__global__ __launch_bounds__(256) void matvec_dual_kernel(
        const float* __restrict__ Wa, const float* __restrict__ Wb,
        const float* __restrict__ x) {
    int warp = threadIdx.x >> 5, lane = threadIdx.x & 31;
    int row = blockIdx.x * 8 + warp;
    const float* W; float* out; int r;
    if (row < DIM_CA3) { W = Wa; out = g_h1; r = row; }
    else               { W = Wb; out = g_h3; r = row - DIM_CA3; }
    const float4* w4 = reinterpret_cast<const float4*>(W) + (size_t)r * (DIM_EI / 4);
    const float4* x4 = reinterpret_cast<const float4*>(x);
    float acc = 0.0f;
    #pragma unroll 8
    for (int i = lane; i < DIM_EI / 4; i += 32) {
        float4 w = __ldcs(&w4[i]);
        float4 v = __ldg(&x4[i]);
        acc += w.x * v.x + w.y * v.y + w.z * v.z + w.w * v.w;
    }
    #pragma unroll
    for (int o = 16; o; o >>= 1) acc += __shfl_down_sync(0xffffffffu, acc, o);
    if (lane == 0) out[r] = acc;
}

// ---------------- K2: block0 -> 2nd-max(h1) tournament + x_ca3 + compaction;
//                      block1 -> top-100(h3) fast radix + IS --------------------------
__global__ void stageA_kernel() {
    int lane = threadIdx.x & 31, wid = threadIdx.x >> 5;
    int base = threadIdx.x * 8;
    if (blockIdx.x == 0) {
        // ---- tournament (max, 2nd max) ----
        float xv[8];
        float m1 = -1e38f, m2 = -1e38f;
        #pragma unroll
        for (int j = 0; j < 8; j++) {
            float v = g_h1[base + j]; xv[j] = v;
            if (v > m1)      { m2 = m1; m1 = v; }
            else if (v > m2) { m2 = v; }
        }
        #pragma unroll
        for (int o = 16; o; o >>= 1) {
            float o1 = __shfl_down_sync(0xffffffffu, m1, o);
            float o2 = __shfl_down_sync(0xffffffffu, m2, o);
            float big = fmaxf(m1, o1);
            float sec = fmaxf(fminf(m1, o1), fmaxf(m2, o2));
            m1 = big; m2 = sec;
        }
        __shared__ float sm1[32], sm2[32];
        __shared__ float s_th;
        if (lane == 0) { sm1[wid] = m1; sm2[wid] = m2; }
        __syncthreads();
        if (threadIdx.x < 32) {
            float a1 = sm1[lane], a2 = sm2[lane];
            #pragma unroll
            for (int o = 16; o; o >>= 1) {
                float o1 = __shfl_down_sync(0xffffffffu, a1, o);
                float o2 = __shfl_down_sync(0xffffffffu, a2, o);
                float big = fmaxf(a1, o1);
                float sec = fmaxf(fminf(a1, o1), fmaxf(a2, o2));
                a1 = big; a2 = sec;
            }
            if (lane == 0) s_th = a2;   // 2nd largest = K=2 threshold
        }
        __syncthreads();
        float th = s_th;
        // ---- mask + sigmoid + deterministic compaction ----
        float vals[8]; int keep[8]; int cnt = 0;
        #pragma unroll
        for (int j = 0; j < 8; j++) {
            int kp = (xv[j] >= th);
            float v = kp ? sigm(BETA * (xv[j] - th)) : 0.0f;
            g_xca3[base + j] = v;
            vals[j] = v; keep[j] = kp; cnt += kp;
        }
        __shared__ int wsum[32];
        int incl = cnt;
        #pragma unroll
        for (int o = 1; o < 32; o <<= 1) {
            int n = __shfl_up_sync(0xffffffffu, incl, o);
            if (lane >= o) incl += n;
        }
        if (lane == 31) wsum[wid] = incl;
        __syncthreads();
        if (threadIdx.x == 0) {
            int s = 0;
            #pragma unroll
            for (int i = 0; i < 32; i++) { int c = wsum[i]; wsum[i] = s; s += c; }
            g_nnz_cnt = s;
        }
        __syncthreads();
        int off = wsum[wid] + incl - cnt;
        #pragma unroll
        for (int j = 0; j < 8; j++)
            if (keep[j]) { g_nnz_idx[off] = base + j; g_nnz_val[off] = vals[j]; ++off; }
    } else {
        float xv[8]; unsigned uv[8];
        #pragma unroll
        for (int j = 0; j < 8; j++) { xv[j] = g_h3[base + j]; uv[j] = f2u(xv[j]); }
        float th = kth_fast_reg<8>(uv, 100);
        #pragma unroll
        for (int j = 0; j < 8; j++)
            g_IS[base + j] = (xv[j] >= th) ? sigm(BETA * (xv[j] - th)) : 0.0f;
    }
}

// ---------------- gather h2 across 32 blocks (spreads L1tex wavefront pressure) -------
__global__ void gather_h2_kernel(const float* __restrict__ W3) {
    int i = blockIdx.x * blockDim.x + threadIdx.x;   // one row per thread (32x256=8192)
    int cnt = g_nnz_cnt;
    size_t rowoff = (size_t)i * DIM_CA3;
    float acc = 0.0f;
    for (int k = 0; k < cnt; k++)
        acc += __ldg(&W3[rowoff + g_nnz_idx[k]]) * g_nnz_val[k];
    g_h2[i] = acc;
}

// ---------------- stageC: top-100(h2) + dense sigmoid -> x_ca1 ------------------------
__global__ void stageC_kernel() {
    int base = threadIdx.x * 8;
    float xv[8]; unsigned uv[8];
    #pragma unroll
    for (int j = 0; j < 8; j++) { xv[j] = g_h2[base + j]; uv[j] = f2u(xv[j]); }
    float th = kth_fast_reg<8>(uv, 100);
    #pragma unroll
    for (int j = 0; j < 8; j++)
        g_xca1[base + j] = sigm(BETA * (xv[j] - th));   // flag=False: no hard mask
}

// ---------------- update_W: (1-IS*a)*W + a*IS*x_ca3^T ----------------
__global__ void update_W_kernel(const float* __restrict__ W, float* __restrict__ out) {
    size_t idx = ((size_t)blockIdx.x * blockDim.x + threadIdx.x) * 4;
    int row = (int)(idx >> 13);
    int col = (int)(idx & (DIM_CA3 - 1));
    float s = g_IS[row];
    float a = 1.0f - s * ALPHA;
    float b = ALPHA * s;
    float4 w  = __ldcs(reinterpret_cast<const float4*>(W + idx));
    float4 xc = *reinterpret_cast<const float4*>(g_xca3 + col);
    float4 o;
    o.x = a * w.x + b * xc.x;
    o.y = a * w.y + b * xc.y;
    o.z = a * w.z + b * xc.z;
    o.w = a * w.w + b * xc.w;
    __stcs(reinterpret_cast<float4*>(out + idx), o);
}

// ---------------- matvec_out + fused top-50 tail ----------------
__global__ __launch_bounds__(256) void matvec_out_kernel(
        const float* __restrict__ W, float* __restrict__ out) {
    int warp = threadIdx.x >> 5, lane = threadIdx.x & 31;
    int tid = threadIdx.x;
    int row = blockIdx.x * 8 + warp;
    const float4* w4 = reinterpret_cast<const float4*>(W) + (size_t)row * (DIM_CA1 / 4);
    const float4* x4 = reinterpret_cast<const float4*>(g_xca1);
    float acc = 0.0f;
    #pragma unroll 8
    for (int i = lane; i < DIM_CA1 / 4; i += 32) {
        float4 w = __ldcs(&w4[i]);
        float4 v = __ldg(&x4[i]);
        acc += w.x * v.x + w.y * v.y + w.z * v.z + w.w * v.w;
    }
    #pragma unroll
    for (int o = 16; o; o >>= 1) acc += __shfl_down_sync(0xffffffffu, acc, o);
    if (lane == 0) {
        g_h4[row] = acc;
        __threadfence();
    }
    __syncthreads();
    __shared__ bool s_last;
    if (tid == 0) {
        unsigned t = atomicAdd(&g_ctr_out, 1u);
        s_last = (t == gridDim.x - 1);
    }
    __syncthreads();
    if (!s_last) return;
    __threadfence();
    float th = kth_fast_global(g_h4, DIM_EO, 50);
    for (int i = tid; i < DIM_EO; i += 256) {
        float xx = g_h4[i];
        out[i] = (xx >= th) ? sigm(BETA * (xx - th)) : 0.0f;
    }
    if (tid == 0) g_ctr_out = 0;
}

// ---------------- launch: R4 fork-join structure ----------------
extern "C" void kernel_launch(void* const* d_in, const int* in_sizes, int n_in,
                              void* d_out, int out_size) {
    const float* x_ei      = (const float*)d_in[0];
    const float* W_ei_ca3  = (const float*)d_in[1];
    const float* W_ei_ca1  = (const float*)d_in[2];
    const float* W_ca3_ca1 = (const float*)d_in[3];
    const float* W_ca1_eo  = (const float*)d_in[4];
    float* out = (float*)d_out;

    cudaStream_t s1;
    cudaStreamCreateWithFlags(&s1, cudaStreamNonBlocking);
    cudaEvent_t e_fork, e_join;
    cudaEventCreateWithFlags(&e_fork, cudaEventDisableTiming);
    cudaEventCreateWithFlags(&e_join, cudaEventDisableTiming);

    matvec_dual_kernel<<<(DIM_CA3 + DIM_CA1) / 8, 256>>>(W_ei_ca3, W_ei_ca1, x_ei);
    stageA_kernel<<<2, 1024>>>();

    // fork: B-chain on s1, concurrent with update_W on stream0
    cudaEventRecord(e_fork, 0);
    cudaStreamWaitEvent(s1, e_fork, 0);

    gather_h2_kernel<<<32, 256, 0, s1>>>(W_ca3_ca1);
    stageC_kernel<<<1, 1024, 0, s1>>>();
    matvec_out_kernel<<<DIM_EO / 8, 256, 0, s1>>>(W_ca1_eo, out);

    update_W_kernel<<<(unsigned)((size_t)DIM_CA1 * DIM_CA3 / 4 / 256), 256>>>(W_ca3_ca1, out + DIM_EO);

    // join
    cudaEventRecord(e_join, s1);
    cudaStreamWaitEvent(0, e_join, 0);

    cudaEventDestroy(e_fork);
    cudaEventDestroy(e_join);
    cudaStreamDestroy(s1);
}